// round 3
// baseline (speedup 1.0000x reference)
#include <cuda_runtime.h>

// BiGRU: B=64, S=4096, D_in=7, H=128, 2 layers, bidirectional, fp32.
//   k_gx0 : gx0 = x @ Wih0^T + bih0 (both dirs)        -> g_gx [tok][768]
//   k_rec : per-(batch,dir) recurrence, 128 CTAs, weights in regs (f32x2),
//           2 rows x half-h per thread (halved LDS), smem partial combine
//   k_gemm: gx1 = h1in @ Wih1^T + bih1 (SIMT f32x2)    -> g_gx (reused)
//   k_rec : layer 1
//   k_head: logits = h1out @ wout^T + bout

#define BB   64
#define SS   4096
#define DIN  7
#define HH   128
#define G3   384
#define NTOK (BB * SS)          // 262144

// ---------------- scratch (device globals; reused across phases) -------------
__device__ float g_gx [ (size_t)NTOK * 768 ];   // gate pre-activations [f384|b384]
__device__ float g_hio[ (size_t)NTOK * 256 ];   // layer in/out hidden  [f128|b128]

// ---------------- f32x2 helpers ----------------------------------------------
__device__ __forceinline__ unsigned long long ffma2(unsigned long long a,
                                                    unsigned long long b,
                                                    unsigned long long c) {
    unsigned long long d;
    asm("fma.rn.f32x2 %0, %1, %2, %3;" : "=l"(d) : "l"(a), "l"(b), "l"(c));
    return d;
}
__device__ __forceinline__ unsigned long long dup2(float x) {
    unsigned long long d;
    asm("mov.b64 %0, {%1, %1};" : "=l"(d) : "f"(x));
    return d;
}
__device__ __forceinline__ float2 unpk(unsigned long long v) {
    float2 r;
    asm("mov.b64 {%0, %1}, %2;" : "=f"(r.x), "=f"(r.y) : "l"(v));
    return r;
}

__device__ __forceinline__ float sigf(float x) {
    return __fdividef(1.f, 1.f + __expf(-x));
}
__device__ __forceinline__ float tanhfast(float x) {
    // tanh(x) = 1 - 2/(e^{2x}+1); saturates cleanly for |x| large
    return 1.f - __fdividef(2.f, __expf(2.f * x) + 1.f);
}

// ---------------- layer-0 input projection (K=7) ------------------------------
__global__ void k_gx0(const float* __restrict__ x,
                      const float* __restrict__ wf, const float* __restrict__ bf,
                      const float* __restrict__ wb, const float* __restrict__ bb) {
    __shared__ float sx[8 * DIN];
    int j = threadIdx.x;                       // 0..767
    long long token0 = (long long)blockIdx.x * 8;
    int dir = (j >= G3);
    int jj = dir ? j - G3 : j;
    const float* wrow = (dir ? wb : wf) + jj * DIN;
    float w0 = wrow[0], w1 = wrow[1], w2 = wrow[2], w3 = wrow[3];
    float w4 = wrow[4], w5 = wrow[5], w6 = wrow[6];
    float bias = (dir ? bb : bf)[jj];
    if (j < 8 * DIN) sx[j] = x[token0 * DIN + j];
    __syncthreads();
#pragma unroll
    for (int tk = 0; tk < 8; tk++) {
        const float* xs = sx + tk * DIN;
        float v = bias;
        v = fmaf(w0, xs[0], v); v = fmaf(w1, xs[1], v); v = fmaf(w2, xs[2], v);
        v = fmaf(w3, xs[3], v); v = fmaf(w4, xs[4], v); v = fmaf(w5, xs[5], v);
        v = fmaf(w6, xs[6], v);
        g_gx[(token0 + tk) * 768 + j] = v;
    }
}

// ---------------- recurrence: one CTA per (batch, dir) ------------------------
// 384 threads. Thread owns 2 gate-rows restricted to ONE half of h:
//   warp parity -> h-half; rows: rbase=(warp>>1)*32+lane and rbase+192.
// Per step: 64 ffma2 (same FMA work as before) but only 16 LDS.128 (halved).
// Row partials combined via smem; gate threads (j<128) finish rows + gates.
__global__ void __launch_bounds__(384, 1) k_rec(
    const float* __restrict__ whh_f, const float* __restrict__ bhh_f,
    const float* __restrict__ whh_b, const float* __restrict__ bhh_b) {
    __shared__ __align__(16) float s_h[HH];
    __shared__ float s_p[2][G3];

    int j    = threadIdx.x;
    int warp = j >> 5;
    int lane = j & 31;
    int b    = blockIdx.x >> 1;
    int dir  = blockIdx.x & 1;

    const float* whh  = dir ? whh_b : whh_f;
    const float* bhhp = dir ? bhh_b : bhh_f;

    int half  = warp & 1;                       // which half of h this warp reads
    int rbase = (warp >> 1) * 32 + lane;        // 0..191
    int row1  = rbase;
    int row2  = rbase + 192;

    // weights: 2 rows x 64 cols = 64 f32x2 pairs = 128 regs
    unsigned long long w1[32], w2[32];
    {
        const unsigned long long* wp1 =
            (const unsigned long long*)(whh + (size_t)row1 * HH + half * 64);
        const unsigned long long* wp2 =
            (const unsigned long long*)(whh + (size_t)row2 * HH + half * 64);
#pragma unroll
        for (int i = 0; i < 32; i++) { w1[i] = wp1[i]; w2[i] = wp2[i]; }
    }

    long long tokbase = (long long)b * SS;
    int t0 = dir ? (SS - 1) : 0;
    int gstr = dir ? -768 : 768;
    int hstr = dir ? -256 : 256;

    // gate-thread state
    float hreg = 0.f, br = 0.f, bz = 0.f, bn = 0.f;
    float xr = 0.f, xz = 0.f, xn = 0.f;
    const float* gp = g_gx + (tokbase + t0) * 768 + (long long)dir * G3 + j;
    float*       hp = g_hio + (tokbase + t0) * 256 + (long long)dir * HH + j;
    if (j < HH) {
        s_h[j] = 0.f;
        br = bhhp[j]; bz = bhhp[HH + j]; bn = bhhp[2 * HH + j];
        xr = gp[0]; xz = gp[HH]; xn = gp[2 * HH];      // prefetch t0 gates
    }
    __syncthreads();

    for (int tt = 0; tt < SS; tt++) {
        // ---- FMA burst: 2 row-halves, 4 independent chains ----
        unsigned long long a0 = 0ull, a1 = 0ull, c0 = 0ull, c1 = 0ull;
        const ulonglong2* hv = (const ulonglong2*)(s_h + half * 64);
#pragma unroll
        for (int k = 0; k < 16; k++) {
            ulonglong2 hk = hv[k];              // LDS.128, broadcast in warp
            a0 = ffma2(w1[2 * k],     hk.x, a0);
            a1 = ffma2(w1[2 * k + 1], hk.y, a1);
            c0 = ffma2(w2[2 * k],     hk.x, c0);
            c1 = ffma2(w2[2 * k + 1], hk.y, c1);
        }
        {
            float2 f0 = unpk(a0), f1 = unpk(a1);
            s_p[half][row1] = (f0.x + f0.y) + (f1.x + f1.y);
            float2 g0 = unpk(c0), g1 = unpk(c1);
            s_p[half][row2] = (g0.x + g0.y) + (g1.x + g1.y);
        }
        __syncthreads();

        if (j < HH) {
            // prefetch next step's gx early (hides DRAM under gates + next burst)
            float nxr = 0.f, nxz = 0.f, nxn = 0.f;
            if (tt + 1 < SS) {
                gp += gstr;
                nxr = gp[0]; nxz = gp[HH]; nxn = gp[2 * HH];
            }
            float hr = s_p[0][j]          + s_p[1][j]          + br;
            float hz = s_p[0][HH + j]     + s_p[1][HH + j]     + bz;
            float hn = s_p[0][2 * HH + j] + s_p[1][2 * HH + j] + bn;
            float r = sigf(xr + hr);
            float z = sigf(xz + hz);
            float n = tanhfast(fmaf(r, hn, xn));
            hreg = fmaf(z, hreg - n, n);         // (1-z)*n + z*h
            s_h[j] = hreg;
            *hp = hreg;
            hp += hstr;
            xr = nxr; xz = nxz; xn = nxn;
        }
        __syncthreads();
    }
}

// ---------------- layer-1 input GEMM: gx1 = h1in @ Wih1^T + bih1 --------------
// C[262144 x 768] = A[262144 x 256] * W[768 x 256]^T ; tiles 128x128x16,
// 256 threads, 8x8 per thread with packed f32x2 accumulators, 2 CTAs/SM.
__global__ void __launch_bounds__(256, 2) k_gemm(
    const float* __restrict__ Wf, const float* __restrict__ bf,
    const float* __restrict__ Wb, const float* __restrict__ bb) {
    __shared__ __align__(16) float As[16][132];
    __shared__ __align__(16) float Bs[16][132];

    int tid = threadIdx.x;
    int mt = blockIdx.x, nt = blockIdx.y;
    const float* W    = (nt < 3) ? Wf : Wb;
    const float* bias = (nt < 3) ? bf : bb;
    int n0loc = (nt % 3) * 128;                  // row offset inside W (per dir)
    long long m0 = (long long)mt * 128;
    const float* Ab = g_hio + m0 * 256;

    int ty = tid >> 4;                           // m-group 0..15
    int tx = tid & 15;                           // n-group 0..15

    unsigned long long acc[8][4];
#pragma unroll
    for (int i = 0; i < 8; i++)
#pragma unroll
        for (int p = 0; p < 4; p++) acc[i][p] = 0ull;

    for (int kt = 0; kt < 256; kt += 16) {
#pragma unroll
        for (int i = 0; i < 2; i++) {
            int task = tid + i * 256;            // 512 float4 loads each for A and W
            int m = task >> 2, kc = task & 3;
            float4 v = *(const float4*)(Ab + (size_t)m * 256 + kt + kc * 4);
            As[kc * 4 + 0][m] = v.x; As[kc * 4 + 1][m] = v.y;
            As[kc * 4 + 2][m] = v.z; As[kc * 4 + 3][m] = v.w;
            float4 u = *(const float4*)(W + (size_t)(n0loc + m) * 256 + kt + kc * 4);
            Bs[kc * 4 + 0][m] = u.x; Bs[kc * 4 + 1][m] = u.y;
            Bs[kc * 4 + 2][m] = u.z; Bs[kc * 4 + 3][m] = u.w;
        }
        __syncthreads();
#pragma unroll
        for (int k = 0; k < 16; k++) {
            float4 va0 = *(const float4*)&As[k][ty * 8];
            float4 va1 = *(const float4*)&As[k][ty * 8 + 4];
            ulonglong2 vb0 = *(const ulonglong2*)&Bs[k][tx * 8];
            ulonglong2 vb1 = *(const ulonglong2*)&Bs[k][tx * 8 + 4];
            unsigned long long bp0 = vb0.x, bp1 = vb0.y, bp2 = vb1.x, bp3 = vb1.y;
            float am[8] = {va0.x, va0.y, va0.z, va0.w, va1.x, va1.y, va1.z, va1.w};
#pragma unroll
            for (int m = 0; m < 8; m++) {
                unsigned long long ad = dup2(am[m]);
                acc[m][0] = ffma2(ad, bp0, acc[m][0]);
                acc[m][1] = ffma2(ad, bp1, acc[m][1]);
                acc[m][2] = ffma2(ad, bp2, acc[m][2]);
                acc[m][3] = ffma2(ad, bp3, acc[m][3]);
            }
        }
        __syncthreads();
    }

    int ngl = nt * 128 + tx * 8;                 // global col in [0,768)
    float bias8[8];
#pragma unroll
    for (int q = 0; q < 8; q++) bias8[q] = bias[n0loc + tx * 8 + q];
#pragma unroll
    for (int m = 0; m < 8; m++) {
        long long gm = m0 + ty * 8 + m;
        float* crow = g_gx + gm * 768 + ngl;
        float o[8];
#pragma unroll
        for (int p = 0; p < 4; p++) {
            float2 f = unpk(acc[m][p]);
            o[2 * p]     = f.x + bias8[2 * p];
            o[2 * p + 1] = f.y + bias8[2 * p + 1];
        }
        *(float4*)(crow)     = make_float4(o[0], o[1], o[2], o[3]);
        *(float4*)(crow + 4) = make_float4(o[4], o[5], o[6], o[7]);
    }
}

// ---------------- output head: logits = h1out @ wout^T + bout -----------------
__global__ void k_head(const float* __restrict__ wout,
                       const float* __restrict__ bout,
                       float* __restrict__ out) {
    int warp = threadIdx.x >> 5, lane = threadIdx.x & 31;
    long long token = (long long)blockIdx.x * 8 + warp;
    const float* hrow = g_hio + token * 256;
    float acc = 0.f;
#pragma unroll
    for (int i = 0; i < 8; i++) {
        int c = lane + i * 32;
        acc = fmaf(hrow[c], wout[c], acc);
    }
#pragma unroll
    for (int off = 16; off; off >>= 1)
        acc += __shfl_xor_sync(0xffffffffu, acc, off);
    if (lane == 0) out[token] = acc + bout[0];
}

// ---------------- launch ------------------------------------------------------
extern "C" void kernel_launch(void* const* d_in, const int* in_sizes, int n_in,
                              void* d_out, int out_size) {
    const float* x     = (const float*)d_in[0];
    const float* wih0f = (const float*)d_in[1];
    const float* whh0f = (const float*)d_in[2];
    const float* bih0f = (const float*)d_in[3];
    const float* bhh0f = (const float*)d_in[4];
    const float* wih0b = (const float*)d_in[5];
    const float* whh0b = (const float*)d_in[6];
    const float* bih0b = (const float*)d_in[7];
    const float* bhh0b = (const float*)d_in[8];
    const float* wih1f = (const float*)d_in[9];
    const float* whh1f = (const float*)d_in[10];
    const float* bih1f = (const float*)d_in[11];
    const float* bhh1f = (const float*)d_in[12];
    const float* wih1b = (const float*)d_in[13];
    const float* whh1b = (const float*)d_in[14];
    const float* bih1b = (const float*)d_in[15];
    const float* bhh1b = (const float*)d_in[16];
    const float* wout  = (const float*)d_in[17];
    const float* bout  = (const float*)d_in[18];
    float* out = (float*)d_out;

    k_gx0 <<<NTOK / 8, 768>>>(x, wih0f, bih0f, wih0b, bih0b);
    k_rec <<<128, 384>>>(whh0f, bhh0f, whh0b, bhh0b);
    k_gemm<<<dim3(2048, 6), 256>>>(wih1f, bih1f, wih1b, bih1b);
    k_rec <<<128, 384>>>(whh1f, bhh1f, whh1b, bhh1b);
    k_head<<<NTOK / 8, 256>>>(wout, bout, out);
}

// round 5
// speedup vs baseline: 1.5372x; 1.5372x over previous
#include <cuda_runtime.h>
#include <cuda_bf16.h>
#include <cstdint>

// BiGRU: B=64, S=4096, D_in=7, H=128, 2 layers, bidirectional, fp32.
//   k_gx0    : gx0 = x @ Wih0^T + bih0 (both dirs)     -> g_gx [tok][768]
//   k_rec    : per-(batch,dir) recurrence (round-0 proven version)
//   k_gemm_tc: gx1 = h1in @ Wih1^T + bih1 via mma.sync bf16 3-term split
//   k_rec    : layer 1
//   k_head   : logits = h1out @ wout^T + bout

#define BB   64
#define SS   4096
#define DIN  7
#define HH   128
#define G3   384
#define NTOK (BB * SS)          // 262144

// ---------------- scratch (device globals; reused across phases) -------------
__device__ float g_gx [ (size_t)NTOK * 768 ];   // gate pre-activations [f384|b384]
__device__ float g_hio[ (size_t)NTOK * 256 ];   // layer in/out hidden  [f128|b128]

// ---------------- f32x2 helpers ----------------------------------------------
__device__ __forceinline__ unsigned long long ffma2(unsigned long long a,
                                                    unsigned long long b,
                                                    unsigned long long c) {
    unsigned long long d;
    asm("fma.rn.f32x2 %0, %1, %2, %3;" : "=l"(d) : "l"(a), "l"(b), "l"(c));
    return d;
}
__device__ __forceinline__ float2 unpk(unsigned long long v) {
    float2 r;
    asm("mov.b64 {%0, %1}, %2;" : "=f"(r.x), "=f"(r.y) : "l"(v));
    return r;
}
__device__ __forceinline__ float sigf(float x) {
    return __fdividef(1.f, 1.f + __expf(-x));
}
__device__ __forceinline__ float tanhfast(float x) {
    return 1.f - __fdividef(2.f, __expf(2.f * x) + 1.f);
}

// ---------------- warp-MMA helpers (baseline PTX, sm_80+) ---------------------
__device__ __forceinline__ uint32_t smem_u32(const void* p) {
    uint32_t a;
    asm("{ .reg .u64 t; cvta.to.shared.u64 t, %1; cvt.u32.u64 %0, t; }"
        : "=r"(a) : "l"(p));
    return a;
}
__device__ __forceinline__ void ldmx4(uint32_t& r0, uint32_t& r1,
                                      uint32_t& r2, uint32_t& r3, uint32_t addr) {
    asm volatile("ldmatrix.sync.aligned.m8n8.x4.shared.b16 {%0,%1,%2,%3}, [%4];"
                 : "=r"(r0), "=r"(r1), "=r"(r2), "=r"(r3) : "r"(addr));
}
__device__ __forceinline__ void mma_bf16(float* d, const uint32_t* a,
                                         const uint32_t* b) {
    asm volatile("mma.sync.aligned.m16n8k16.row.col.f32.bf16.bf16.f32 "
                 "{%0,%1,%2,%3}, {%4,%5,%6,%7}, {%8,%9}, {%0,%1,%2,%3};"
                 : "+f"(d[0]), "+f"(d[1]), "+f"(d[2]), "+f"(d[3])
                 : "r"(a[0]), "r"(a[1]), "r"(a[2]), "r"(a[3]),
                   "r"(b[0]), "r"(b[1]));
}

// ---------------- layer-0 input projection (K=7) ------------------------------
__global__ void k_gx0(const float* __restrict__ x,
                      const float* __restrict__ wf, const float* __restrict__ bf,
                      const float* __restrict__ wb, const float* __restrict__ bb) {
    __shared__ float sx[8 * DIN];
    int j = threadIdx.x;                       // 0..767
    long long token0 = (long long)blockIdx.x * 8;
    int dir = (j >= G3);
    int jj = dir ? j - G3 : j;
    const float* wrow = (dir ? wb : wf) + jj * DIN;
    float w0 = wrow[0], w1 = wrow[1], w2 = wrow[2], w3 = wrow[3];
    float w4 = wrow[4], w5 = wrow[5], w6 = wrow[6];
    float bias = (dir ? bb : bf)[jj];
    if (j < 8 * DIN) sx[j] = x[token0 * DIN + j];
    __syncthreads();
#pragma unroll
    for (int tk = 0; tk < 8; tk++) {
        const float* xs = sx + tk * DIN;
        float v = bias;
        v = fmaf(w0, xs[0], v); v = fmaf(w1, xs[1], v); v = fmaf(w2, xs[2], v);
        v = fmaf(w3, xs[3], v); v = fmaf(w4, xs[4], v); v = fmaf(w5, xs[5], v);
        v = fmaf(w6, xs[6], v);
        g_gx[(token0 + tk) * 768 + j] = v;
    }
}

// ---------------- recurrence (round-0 proven version) -------------------------
__global__ void __launch_bounds__(384, 1) k_rec(
    const float* __restrict__ whh_f, const float* __restrict__ bhh_f,
    const float* __restrict__ whh_b, const float* __restrict__ bhh_b) {
    __shared__ __align__(16) float s_h[HH];
    __shared__ float s_a[G3];
    __shared__ float s_b[G3];

    int j   = threadIdx.x;
    int b   = blockIdx.x >> 1;
    int dir = blockIdx.x & 1;

    const float* whh = dir ? whh_b : whh_f;
    float bhh = (dir ? bhh_b : bhh_f)[j];

    unsigned long long w[64];
    const unsigned long long* wp =
        (const unsigned long long*)(whh + (size_t)j * HH);
#pragma unroll
    for (int i = 0; i < 64; i++) w[i] = wp[i];

    if (j < HH) s_h[j] = 0.f;
    float hreg = 0.f;

    long long tokbase = (long long)b * SS;
    int t0 = dir ? (SS - 1) : 0;
    long long gstr = dir ? -768 : 768;
    long long hstr = dir ? -256 : 256;

    const float* gp = g_gx + (tokbase + t0) * 768 + (long long)dir * G3 + j;
    float*       hp = g_hio + (tokbase + t0) * 256 + (long long)dir * HH + j;

    float gx_next = *gp;
    __syncthreads();

    for (int tt = 0; tt < SS; tt++) {
        float gxv = gx_next;
        gp += gstr;
        if (tt + 1 < SS) gx_next = *gp;          // prefetch next step

        unsigned long long a0 = 0ull, a1 = 0ull;
        const ulonglong2* hv = (const ulonglong2*)s_h;
#pragma unroll
        for (int k = 0; k < 32; k++) {
            ulonglong2 hk = hv[k];               // LDS.128, warp-uniform broadcast
            a0 = ffma2(w[2 * k],     hk.x, a0);
            a1 = ffma2(w[2 * k + 1], hk.y, a1);
        }
        float2 f0 = unpk(a0), f1 = unpk(a1);
        float gh = (f0.x + f0.y) + (f1.x + f1.y) + bhh;

        s_a[j] = gxv;
        s_b[j] = gh;
        __syncthreads();

        if (j < HH) {
            float r = sigf(s_a[j]        + s_b[j]);
            float z = sigf(s_a[HH + j]   + s_b[HH + j]);
            float n = tanhfast(fmaf(r, s_b[2 * HH + j], s_a[2 * HH + j]));
            hreg = fmaf(z, hreg - n, n);
            s_h[j] = hreg;
            *hp = hreg;
            hp += hstr;
        }
        __syncthreads();
    }
}

// ---------------- layer-1 GEMM via mma.sync (bf16 3-term split) ----------------
// C[262144 x 768] = A[262144 x 256] * W[768 x 256]^T + bias
// CTA tile M=128, N=256 (grid.y = 3), 8 warps as 2x4 (warp tile 64x64),
// K in 16 chunks of 16. fp32 -> bf16 hi/lo split done during smem fill.
// acc += Ah*Bh + Ah*Bl + Al*Bh  (fp32 accumulate, ~1.5e-5 rel error)
#define ASTR 24          // smem row stride in bf16 elems (48B: aligned, no conflicts)

__global__ void __launch_bounds__(256, 1) k_gemm_tc(
    const float* __restrict__ Wf, const float* __restrict__ bf,
    const float* __restrict__ Wb, const float* __restrict__ bb) {
    __shared__ __align__(16) __nv_bfloat16 Ah[128][ASTR];
    __shared__ __align__(16) __nv_bfloat16 Al[128][ASTR];
    __shared__ __align__(16) __nv_bfloat16 Bh[256][ASTR];
    __shared__ __align__(16) __nv_bfloat16 Bl[256][ASTR];

    int tid = threadIdx.x, wid = tid >> 5, lane = tid & 31;
    long long m0 = (long long)blockIdx.x * 128;
    int n0 = blockIdx.y * 256;
    int wm = wid >> 2, wn = wid & 3;             // warp 64x64 tile at (wm*64, wn*64)

    // ldmatrix per-lane smem offsets (bytes)
    uint32_t aoff = (uint32_t)(((wm * 64 + (lane & 15)) * ASTR + (lane >> 4) * 8) * 2);
    uint32_t boff = (uint32_t)(((wn * 64 + (lane & 7) + ((lane >> 4) << 3)) * ASTR
                                + ((lane >> 3) & 1) * 8) * 2);
    uint32_t ah_a = smem_u32(Ah) + aoff, al_a = smem_u32(Al) + aoff;
    uint32_t bh_a = smem_u32(Bh) + boff, bl_a = smem_u32(Bl) + boff;

    float acc[4][8][4];
#pragma unroll
    for (int i = 0; i < 4; i++)
#pragma unroll
        for (int j = 0; j < 8; j++)
#pragma unroll
            for (int q = 0; q < 4; q++) acc[i][j][q] = 0.f;

    // prefetch regs: A 2 float4, B 4 float4
    float4 pA[2], pB[4];
#pragma unroll
    for (int i = 0; i < 2; i++) {
        int task = tid + i * 256, row = task >> 2, c4 = task & 3;
        pA[i] = *(const float4*)(g_hio + (m0 + row) * 256 + c4 * 4);
    }
#pragma unroll
    for (int i = 0; i < 4; i++) {
        int task = tid + i * 256, row = task >> 2, c4 = task & 3;
        int n = n0 + row;
        const float* src = (n < 384) ? (Wf + (size_t)n * 256)
                                     : (Wb + (size_t)(n - 384) * 256);
        pB[i] = *(const float4*)(src + c4 * 4);
    }

    for (int ck = 0; ck < 16; ck++) {
        // ---- convert + store current chunk to smem ----
#pragma unroll
        for (int i = 0; i < 2; i++) {
            int task = tid + i * 256, row = task >> 2, c4 = task & 3;
            float4 v = pA[i];
            __nv_bfloat16 hx = __float2bfloat16(v.x), hy = __float2bfloat16(v.y);
            __nv_bfloat16 hz = __float2bfloat16(v.z), hw = __float2bfloat16(v.w);
            __nv_bfloat162 h01 = __halves2bfloat162(hx, hy);
            __nv_bfloat162 h23 = __halves2bfloat162(hz, hw);
            __nv_bfloat162 l01 = __halves2bfloat162(
                __float2bfloat16(v.x - __bfloat162float(hx)),
                __float2bfloat16(v.y - __bfloat162float(hy)));
            __nv_bfloat162 l23 = __halves2bfloat162(
                __float2bfloat16(v.z - __bfloat162float(hz)),
                __float2bfloat16(v.w - __bfloat162float(hw)));
            *(uint2*)&Ah[row][c4 * 4] = make_uint2(*(uint32_t*)&h01, *(uint32_t*)&h23);
            *(uint2*)&Al[row][c4 * 4] = make_uint2(*(uint32_t*)&l01, *(uint32_t*)&l23);
        }
#pragma unroll
        for (int i = 0; i < 4; i++) {
            int task = tid + i * 256, row = task >> 2, c4 = task & 3;
            float4 v = pB[i];
            __nv_bfloat16 hx = __float2bfloat16(v.x), hy = __float2bfloat16(v.y);
            __nv_bfloat16 hz = __float2bfloat16(v.z), hw = __float2bfloat16(v.w);
            __nv_bfloat162 h01 = __halves2bfloat162(hx, hy);
            __nv_bfloat162 h23 = __halves2bfloat162(hz, hw);
            __nv_bfloat162 l01 = __halves2bfloat162(
                __float2bfloat16(v.x - __bfloat162float(hx)),
                __float2bfloat16(v.y - __bfloat162float(hy)));
            __nv_bfloat162 l23 = __halves2bfloat162(
                __float2bfloat16(v.z - __bfloat162float(hz)),
                __float2bfloat16(v.w - __bfloat162float(hw)));
            *(uint2*)&Bh[row][c4 * 4] = make_uint2(*(uint32_t*)&h01, *(uint32_t*)&h23);
            *(uint2*)&Bl[row][c4 * 4] = make_uint2(*(uint32_t*)&l01, *(uint32_t*)&l23);
        }
        __syncthreads();

        // ---- prefetch next chunk (consumed next iteration; hidden by MMAs) ----
        if (ck + 1 < 16) {
            int kc = (ck + 1) * 16;
#pragma unroll
            for (int i = 0; i < 2; i++) {
                int task = tid + i * 256, row = task >> 2, c4 = task & 3;
                pA[i] = *(const float4*)(g_hio + (m0 + row) * 256 + kc + c4 * 4);
            }
#pragma unroll
            for (int i = 0; i < 4; i++) {
                int task = tid + i * 256, row = task >> 2, c4 = task & 3;
                int n = n0 + row;
                const float* src = (n < 384) ? (Wf + (size_t)n * 256)
                                             : (Wb + (size_t)(n - 384) * 256);
                pB[i] = *(const float4*)(src + kc + c4 * 4);
            }
        }

        // ---- 3 split terms: (Ah,Bh), (Ah,Bl), (Al,Bh) ----
#pragma unroll
        for (int term = 0; term < 3; term++) {
            uint32_t aAddr = (term == 2) ? al_a : ah_a;
            uint32_t bAddr = (term == 1) ? bl_a : bh_a;
            uint32_t afr[4][4];
#pragma unroll
            for (int mf = 0; mf < 4; mf++)
                ldmx4(afr[mf][0], afr[mf][1], afr[mf][2], afr[mf][3],
                      aAddr + mf * (16 * ASTR * 2));
            uint32_t bfr[8][2];
#pragma unroll
            for (int p = 0; p < 4; p++) {
                uint32_t r0, r1, r2, r3;
                ldmx4(r0, r1, r2, r3, bAddr + p * (16 * ASTR * 2));
                bfr[2 * p][0] = r0; bfr[2 * p][1] = r1;
                bfr[2 * p + 1][0] = r2; bfr[2 * p + 1][1] = r3;
            }
#pragma unroll
            for (int mf = 0; mf < 4; mf++)
#pragma unroll
                for (int nf = 0; nf < 8; nf++)
                    mma_bf16(acc[mf][nf], afr[mf], bfr[nf]);
        }
        __syncthreads();
    }

    // ---- epilogue: acc + bias -> g_gx ----
    int g = lane >> 2, c2 = (lane & 3) * 2;
    float bias2[8][2];
#pragma unroll
    for (int nf = 0; nf < 8; nf++) {
        int col = n0 + wn * 64 + nf * 8 + c2;
        bias2[nf][0] = (col < 384) ? bf[col] : bb[col - 384];
        bias2[nf][1] = (col + 1 < 384) ? bf[col + 1] : bb[col + 1 - 384];
    }
#pragma unroll
    for (int mf = 0; mf < 4; mf++) {
        long long r0 = m0 + wm * 64 + mf * 16 + g;
#pragma unroll
        for (int nf = 0; nf < 8; nf++) {
            int col = n0 + wn * 64 + nf * 8 + c2;
            *(float2*)&g_gx[r0 * 768 + col] =
                make_float2(acc[mf][nf][0] + bias2[nf][0],
                            acc[mf][nf][1] + bias2[nf][1]);
            *(float2*)&g_gx[(r0 + 8) * 768 + col] =
                make_float2(acc[mf][nf][2] + bias2[nf][0],
                            acc[mf][nf][3] + bias2[nf][1]);
        }
    }
}

// ---------------- output head: logits = h1out @ wout^T + bout -----------------
__global__ void k_head(const float* __restrict__ wout,
                       const float* __restrict__ bout,
                       float* __restrict__ out) {
    int warp = threadIdx.x >> 5, lane = threadIdx.x & 31;
    long long token = (long long)blockIdx.x * 8 + warp;
    const float* hrow = g_hio + token * 256;
    float acc = 0.f;
#pragma unroll
    for (int i = 0; i < 8; i++) {
        int c = lane + i * 32;
        acc = fmaf(hrow[c], wout[c], acc);
    }
#pragma unroll
    for (int off = 16; off; off >>= 1)
        acc += __shfl_xor_sync(0xffffffffu, acc, off);
    if (lane == 0) out[token] = acc + bout[0];
}

// ---------------- launch ------------------------------------------------------
extern "C" void kernel_launch(void* const* d_in, const int* in_sizes, int n_in,
                              void* d_out, int out_size) {
    const float* x     = (const float*)d_in[0];
    const float* wih0f = (const float*)d_in[1];
    const float* whh0f = (const float*)d_in[2];
    const float* bih0f = (const float*)d_in[3];
    const float* bhh0f = (const float*)d_in[4];
    const float* wih0b = (const float*)d_in[5];
    const float* whh0b = (const float*)d_in[6];
    const float* bih0b = (const float*)d_in[7];
    const float* bhh0b = (const float*)d_in[8];
    const float* wih1f = (const float*)d_in[9];
    const float* whh1f = (const float*)d_in[10];
    const float* bih1f = (const float*)d_in[11];
    const float* bhh1f = (const float*)d_in[12];
    const float* wih1b = (const float*)d_in[13];
    const float* whh1b = (const float*)d_in[14];
    const float* bih1b = (const float*)d_in[15];
    const float* bhh1b = (const float*)d_in[16];
    const float* wout  = (const float*)d_in[17];
    const float* bout  = (const float*)d_in[18];
    float* out = (float*)d_out;

    k_gx0    <<<NTOK / 8, 768>>>(x, wih0f, bih0f, wih0b, bih0b);
    k_rec    <<<128, 384>>>(whh0f, bhh0f, whh0b, bhh0b);
    k_gemm_tc<<<dim3(2048, 3), 256>>>(wih1f, bih1f, wih1b, bih1b);
    k_rec    <<<128, 384>>>(whh1f, bhh1f, whh1b, bhh1b);
    k_head   <<<NTOK / 8, 256>>>(wout, bout, out);
}

// round 6
// speedup vs baseline: 1.5556x; 1.0120x over previous
#include <cuda_runtime.h>
#include <cuda_bf16.h>
#include <cstdint>

// BiGRU: B=64, S=4096, D_in=7, H=128, 2 layers, bidirectional, fp32.
//   k_gx0    : gx0 = x @ Wih0^T + bih0 (both dirs)     -> g_gx [tok][768]
//   k_rec    : per-(batch,dir) recurrence; 2-step gx prefetch + pre-added gates
//   k_gemm_tc: gx1 = h1in @ Wih1^T + bih1 via mma.sync bf16 3-term split
//   k_rec    : layer 1
//   k_head   : logits = h1out @ wout^T + bout

#define BB   64
#define SS   4096
#define DIN  7
#define HH   128
#define G3   384
#define NTOK (BB * SS)          // 262144

// ---------------- scratch (device globals; reused across phases) -------------
__device__ float g_gx [ (size_t)NTOK * 768 ];   // gate pre-activations [f384|b384]
__device__ float g_hio[ (size_t)NTOK * 256 ];   // layer in/out hidden  [f128|b128]

// ---------------- f32x2 helpers ----------------------------------------------
__device__ __forceinline__ unsigned long long ffma2(unsigned long long a,
                                                    unsigned long long b,
                                                    unsigned long long c) {
    unsigned long long d;
    asm("fma.rn.f32x2 %0, %1, %2, %3;" : "=l"(d) : "l"(a), "l"(b), "l"(c));
    return d;
}
__device__ __forceinline__ float2 unpk(unsigned long long v) {
    float2 r;
    asm("mov.b64 {%0, %1}, %2;" : "=f"(r.x), "=f"(r.y) : "l"(v));
    return r;
}
__device__ __forceinline__ float sigf(float x) {
    return __fdividef(1.f, 1.f + __expf(-x));
}
__device__ __forceinline__ float tanhfast(float x) {
    return 1.f - __fdividef(2.f, __expf(2.f * x) + 1.f);
}

// ---------------- warp-MMA helpers (baseline PTX, sm_80+) ---------------------
__device__ __forceinline__ uint32_t smem_u32(const void* p) {
    uint32_t a;
    asm("{ .reg .u64 t; cvta.to.shared.u64 t, %1; cvt.u32.u64 %0, t; }"
        : "=r"(a) : "l"(p));
    return a;
}
__device__ __forceinline__ void ldmx4(uint32_t& r0, uint32_t& r1,
                                      uint32_t& r2, uint32_t& r3, uint32_t addr) {
    asm volatile("ldmatrix.sync.aligned.m8n8.x4.shared.b16 {%0,%1,%2,%3}, [%4];"
                 : "=r"(r0), "=r"(r1), "=r"(r2), "=r"(r3) : "r"(addr));
}
__device__ __forceinline__ void mma_bf16(float* d, const uint32_t* a,
                                         const uint32_t* b) {
    asm volatile("mma.sync.aligned.m16n8k16.row.col.f32.bf16.bf16.f32 "
                 "{%0,%1,%2,%3}, {%4,%5,%6,%7}, {%8,%9}, {%0,%1,%2,%3};"
                 : "+f"(d[0]), "+f"(d[1]), "+f"(d[2]), "+f"(d[3])
                 : "r"(a[0]), "r"(a[1]), "r"(a[2]), "r"(a[3]),
                   "r"(b[0]), "r"(b[1]));
}

// ---------------- layer-0 input projection (K=7) ------------------------------
__global__ void k_gx0(const float* __restrict__ x,
                      const float* __restrict__ wf, const float* __restrict__ bf,
                      const float* __restrict__ wb, const float* __restrict__ bb) {
    __shared__ float sx[8 * DIN];
    int j = threadIdx.x;                       // 0..767
    long long token0 = (long long)blockIdx.x * 8;
    int dir = (j >= G3);
    int jj = dir ? j - G3 : j;
    const float* wrow = (dir ? wb : wf) + jj * DIN;
    float w0 = wrow[0], w1 = wrow[1], w2 = wrow[2], w3 = wrow[3];
    float w4 = wrow[4], w5 = wrow[5], w6 = wrow[6];
    float bias = (dir ? bb : bf)[jj];
    if (j < 8 * DIN) sx[j] = x[token0 * DIN + j];
    __syncthreads();
#pragma unroll
    for (int tk = 0; tk < 8; tk++) {
        const float* xs = sx + tk * DIN;
        float v = bias;
        v = fmaf(w0, xs[0], v); v = fmaf(w1, xs[1], v); v = fmaf(w2, xs[2], v);
        v = fmaf(w3, xs[3], v); v = fmaf(w4, xs[4], v); v = fmaf(w5, xs[5], v);
        v = fmaf(w6, xs[6], v);
        g_gx[(token0 + tk) * 768 + j] = v;
    }
}

// ---------------- recurrence: one CTA per (batch, dir) ------------------------
// 384 threads; thread j owns gate-row j (64 f32x2 weight regs).
// R6 changes vs round-0 baseline:
//  (1) gx prefetched TWO steps ahead (DRAM 577cyc > one-step tolerance ~400)
//  (2) r/z rows pre-add gx into gh before the smem handoff; n keeps xn separate
__global__ void __launch_bounds__(384, 1) k_rec(
    const float* __restrict__ whh_f, const float* __restrict__ bhh_f,
    const float* __restrict__ whh_b, const float* __restrict__ bhh_b) {
    __shared__ __align__(16) float s_h[HH];
    __shared__ float s_b[G3];
    __shared__ float s_xn[HH];

    int j   = threadIdx.x;
    int b   = blockIdx.x >> 1;
    int dir = blockIdx.x & 1;

    const float* whh = dir ? whh_b : whh_f;
    float bhh = (dir ? bhh_b : bhh_f)[j];

    unsigned long long w[64];
    const unsigned long long* wp =
        (const unsigned long long*)(whh + (size_t)j * HH);
#pragma unroll
    for (int i = 0; i < 64; i++) w[i] = wp[i];

    if (j < HH) s_h[j] = 0.f;
    float hreg = 0.f;

    long long tokbase = (long long)b * SS;
    int t0 = dir ? (SS - 1) : 0;
    long long gstr = dir ? -768 : 768;
    long long hstr = dir ? -256 : 256;

    const float* gp = g_gx + (tokbase + t0) * 768 + (long long)dir * G3 + j;
    float*       hp = g_hio + (tokbase + t0) * 256 + (long long)dir * HH + j;

    float gx_n1 = gp[0];                        // step t
    gp += gstr;
    float gx_n2 = gp[0];                        // step t+1 (SS >= 2)
    __syncthreads();

    for (int tt = 0; tt < SS; tt++) {
        float gxv = gx_n1;
        gx_n1 = gx_n2;
        gp += gstr;
        if (tt + 2 < SS) gx_n2 = *gp;           // 2-step-ahead prefetch

        unsigned long long a0 = 0ull, a1 = 0ull;
        const ulonglong2* hv = (const ulonglong2*)s_h;
#pragma unroll
        for (int k = 0; k < 32; k++) {
            ulonglong2 hk = hv[k];               // LDS.128, warp-uniform broadcast
            a0 = ffma2(w[2 * k],     hk.x, a0);
            a1 = ffma2(w[2 * k + 1], hk.y, a1);
        }
        float2 f0 = unpk(a0), f1 = unpk(a1);
        float gh = (f0.x + f0.y) + (f1.x + f1.y) + bhh;

        if (j < 2 * HH) {
            s_b[j] = gh + gxv;                   // r,z rows: pre-added
        } else {
            s_b[j] = gh;                         // n rows: keep hn separate
            s_xn[j - 2 * HH] = gxv;
        }
        __syncthreads();

        if (j < HH) {
            float r = sigf(s_b[j]);
            float z = sigf(s_b[HH + j]);
            float n = tanhfast(fmaf(r, s_b[2 * HH + j], s_xn[j]));
            hreg = fmaf(z, hreg - n, n);         // (1-z)*n + z*h
            s_h[j] = hreg;
            *hp = hreg;
            hp += hstr;
        }
        __syncthreads();
    }
}

// ---------------- layer-1 GEMM via mma.sync (bf16 3-term split) ----------------
// C[262144 x 768] = A[262144 x 256] * W[768 x 256]^T + bias
// CTA tile M=128, N=256 (grid.y = 3), 8 warps as 2x4 (warp tile 64x64),
// K in 16 chunks of 16. fp32 -> bf16 hi/lo split done during smem fill.
// acc += Ah*Bh + Ah*Bl + Al*Bh  (fp32 accumulate, ~1.5e-5 rel error)
#define ASTR 24          // smem row stride in bf16 elems (48B: aligned, no conflicts)

__global__ void __launch_bounds__(256, 1) k_gemm_tc(
    const float* __restrict__ Wf, const float* __restrict__ bf,
    const float* __restrict__ Wb, const float* __restrict__ bb) {
    __shared__ __align__(16) __nv_bfloat16 Ah[128][ASTR];
    __shared__ __align__(16) __nv_bfloat16 Al[128][ASTR];
    __shared__ __align__(16) __nv_bfloat16 Bh[256][ASTR];
    __shared__ __align__(16) __nv_bfloat16 Bl[256][ASTR];

    int tid = threadIdx.x, wid = tid >> 5, lane = tid & 31;
    long long m0 = (long long)blockIdx.x * 128;
    int n0 = blockIdx.y * 256;
    int wm = wid >> 2, wn = wid & 3;             // warp 64x64 tile at (wm*64, wn*64)

    // ldmatrix per-lane smem offsets (bytes)
    uint32_t aoff = (uint32_t)(((wm * 64 + (lane & 15)) * ASTR + (lane >> 4) * 8) * 2);
    uint32_t boff = (uint32_t)(((wn * 64 + (lane & 7) + ((lane >> 4) << 3)) * ASTR
                                + ((lane >> 3) & 1) * 8) * 2);
    uint32_t ah_a = smem_u32(Ah) + aoff, al_a = smem_u32(Al) + aoff;
    uint32_t bh_a = smem_u32(Bh) + boff, bl_a = smem_u32(Bl) + boff;

    float acc[4][8][4];
#pragma unroll
    for (int i = 0; i < 4; i++)
#pragma unroll
        for (int j = 0; j < 8; j++)
#pragma unroll
            for (int q = 0; q < 4; q++) acc[i][j][q] = 0.f;

    // prefetch regs: A 2 float4, B 4 float4
    float4 pA[2], pB[4];
#pragma unroll
    for (int i = 0; i < 2; i++) {
        int task = tid + i * 256, row = task >> 2, c4 = task & 3;
        pA[i] = *(const float4*)(g_hio + (m0 + row) * 256 + c4 * 4);
    }
#pragma unroll
    for (int i = 0; i < 4; i++) {
        int task = tid + i * 256, row = task >> 2, c4 = task & 3;
        int n = n0 + row;
        const float* src = (n < 384) ? (Wf + (size_t)n * 256)
                                     : (Wb + (size_t)(n - 384) * 256);
        pB[i] = *(const float4*)(src + c4 * 4);
    }

    for (int ck = 0; ck < 16; ck++) {
        // ---- convert + store current chunk to smem ----
#pragma unroll
        for (int i = 0; i < 2; i++) {
            int task = tid + i * 256, row = task >> 2, c4 = task & 3;
            float4 v = pA[i];
            __nv_bfloat16 hx = __float2bfloat16(v.x), hy = __float2bfloat16(v.y);
            __nv_bfloat16 hz = __float2bfloat16(v.z), hw = __float2bfloat16(v.w);
            __nv_bfloat162 h01 = __halves2bfloat162(hx, hy);
            __nv_bfloat162 h23 = __halves2bfloat162(hz, hw);
            __nv_bfloat162 l01 = __halves2bfloat162(
                __float2bfloat16(v.x - __bfloat162float(hx)),
                __float2bfloat16(v.y - __bfloat162float(hy)));
            __nv_bfloat162 l23 = __halves2bfloat162(
                __float2bfloat16(v.z - __bfloat162float(hz)),
                __float2bfloat16(v.w - __bfloat162float(hw)));
            *(uint2*)&Ah[row][c4 * 4] = make_uint2(*(uint32_t*)&h01, *(uint32_t*)&h23);
            *(uint2*)&Al[row][c4 * 4] = make_uint2(*(uint32_t*)&l01, *(uint32_t*)&l23);
        }
#pragma unroll
        for (int i = 0; i < 4; i++) {
            int task = tid + i * 256, row = task >> 2, c4 = task & 3;
            float4 v = pB[i];
            __nv_bfloat16 hx = __float2bfloat16(v.x), hy = __float2bfloat16(v.y);
            __nv_bfloat16 hz = __float2bfloat16(v.z), hw = __float2bfloat16(v.w);
            __nv_bfloat162 h01 = __halves2bfloat162(hx, hy);
            __nv_bfloat162 h23 = __halves2bfloat162(hz, hw);
            __nv_bfloat162 l01 = __halves2bfloat162(
                __float2bfloat16(v.x - __bfloat162float(hx)),
                __float2bfloat16(v.y - __bfloat162float(hy)));
            __nv_bfloat162 l23 = __halves2bfloat162(
                __float2bfloat16(v.z - __bfloat162float(hz)),
                __float2bfloat16(v.w - __bfloat162float(hw)));
            *(uint2*)&Bh[row][c4 * 4] = make_uint2(*(uint32_t*)&h01, *(uint32_t*)&h23);
            *(uint2*)&Bl[row][c4 * 4] = make_uint2(*(uint32_t*)&l01, *(uint32_t*)&l23);
        }
        __syncthreads();

        // ---- prefetch next chunk (consumed next iteration; hidden by MMAs) ----
        if (ck + 1 < 16) {
            int kc = (ck + 1) * 16;
#pragma unroll
            for (int i = 0; i < 2; i++) {
                int task = tid + i * 256, row = task >> 2, c4 = task & 3;
                pA[i] = *(const float4*)(g_hio + (m0 + row) * 256 + kc + c4 * 4);
            }
#pragma unroll
            for (int i = 0; i < 4; i++) {
                int task = tid + i * 256, row = task >> 2, c4 = task & 3;
                int n = n0 + row;
                const float* src = (n < 384) ? (Wf + (size_t)n * 256)
                                             : (Wb + (size_t)(n - 384) * 256);
                pB[i] = *(const float4*)(src + kc + c4 * 4);
            }
        }

        // ---- 3 split terms: (Ah,Bh), (Ah,Bl), (Al,Bh) ----
#pragma unroll
        for (int term = 0; term < 3; term++) {
            uint32_t aAddr = (term == 2) ? al_a : ah_a;
            uint32_t bAddr = (term == 1) ? bl_a : bh_a;
            uint32_t afr[4][4];
#pragma unroll
            for (int mf = 0; mf < 4; mf++)
                ldmx4(afr[mf][0], afr[mf][1], afr[mf][2], afr[mf][3],
                      aAddr + mf * (16 * ASTR * 2));
            uint32_t bfr[8][2];
#pragma unroll
            for (int p = 0; p < 4; p++) {
                uint32_t r0, r1, r2, r3;
                ldmx4(r0, r1, r2, r3, bAddr + p * (16 * ASTR * 2));
                bfr[2 * p][0] = r0; bfr[2 * p][1] = r1;
                bfr[2 * p + 1][0] = r2; bfr[2 * p + 1][1] = r3;
            }
#pragma unroll
            for (int mf = 0; mf < 4; mf++)
#pragma unroll
                for (int nf = 0; nf < 8; nf++)
                    mma_bf16(acc[mf][nf], afr[mf], bfr[nf]);
        }
        __syncthreads();
    }

    // ---- epilogue: acc + bias -> g_gx ----
    int g = lane >> 2, c2 = (lane & 3) * 2;
    float bias2[8][2];
#pragma unroll
    for (int nf = 0; nf < 8; nf++) {
        int col = n0 + wn * 64 + nf * 8 + c2;
        bias2[nf][0] = (col < 384) ? bf[col] : bb[col - 384];
        bias2[nf][1] = (col + 1 < 384) ? bf[col + 1] : bb[col + 1 - 384];
    }
#pragma unroll
    for (int mf = 0; mf < 4; mf++) {
        long long r0 = m0 + wm * 64 + mf * 16 + g;
#pragma unroll
        for (int nf = 0; nf < 8; nf++) {
            int col = n0 + wn * 64 + nf * 8 + c2;
            *(float2*)&g_gx[r0 * 768 + col] =
                make_float2(acc[mf][nf][0] + bias2[nf][0],
                            acc[mf][nf][1] + bias2[nf][1]);
            *(float2*)&g_gx[(r0 + 8) * 768 + col] =
                make_float2(acc[mf][nf][2] + bias2[nf][0],
                            acc[mf][nf][3] + bias2[nf][1]);
        }
    }
}

// ---------------- output head: logits = h1out @ wout^T + bout -----------------
__global__ void k_head(const float* __restrict__ wout,
                       const float* __restrict__ bout,
                       float* __restrict__ out) {
    int warp = threadIdx.x >> 5, lane = threadIdx.x & 31;
    long long token = (long long)blockIdx.x * 8 + warp;
    const float* hrow = g_hio + token * 256;
    float acc = 0.f;
#pragma unroll
    for (int i = 0; i < 8; i++) {
        int c = lane + i * 32;
        acc = fmaf(hrow[c], wout[c], acc);
    }
#pragma unroll
    for (int off = 16; off; off >>= 1)
        acc += __shfl_xor_sync(0xffffffffu, acc, off);
    if (lane == 0) out[token] = acc + bout[0];
}

// ---------------- launch ------------------------------------------------------
extern "C" void kernel_launch(void* const* d_in, const int* in_sizes, int n_in,
                              void* d_out, int out_size) {
    const float* x     = (const float*)d_in[0];
    const float* wih0f = (const float*)d_in[1];
    const float* whh0f = (const float*)d_in[2];
    const float* bih0f = (const float*)d_in[3];
    const float* bhh0f = (const float*)d_in[4];
    const float* wih0b = (const float*)d_in[5];
    const float* whh0b = (const float*)d_in[6];
    const float* bih0b = (const float*)d_in[7];
    const float* bhh0b = (const float*)d_in[8];
    const float* wih1f = (const float*)d_in[9];
    const float* whh1f = (const float*)d_in[10];
    const float* bih1f = (const float*)d_in[11];
    const float* bhh1f = (const float*)d_in[12];
    const float* wih1b = (const float*)d_in[13];
    const float* whh1b = (const float*)d_in[14];
    const float* bih1b = (const float*)d_in[15];
    const float* bhh1b = (const float*)d_in[16];
    const float* wout  = (const float*)d_in[17];
    const float* bout  = (const float*)d_in[18];
    float* out = (float*)d_out;

    k_gx0    <<<NTOK / 8, 768>>>(x, wih0f, bih0f, wih0b, bih0b);
    k_rec    <<<128, 384>>>(whh0f, bhh0f, whh0b, bhh0b);
    k_gemm_tc<<<dim3(2048, 3), 256>>>(wih1f, bih1f, wih1b, bih1b);
    k_rec    <<<128, 384>>>(whh1f, bhh1f, whh1b, bhh1b);
    k_head   <<<NTOK / 8, 256>>>(wout, bout, out);
}